// round 1
// baseline (speedup 1.0000x reference)
#include <cuda_runtime.h>
#include <math.h>
#include <float.h>

#define BATCH 8
#define LSEQ 1024
#define DMODEL 768
#define D2V 1536
#define NSTATE 16
#define ROWS (BATCH*LSEQ)     /* 8192 */
#define K3 (3*LSEQ)           /* 3072 */

// ---------------- scratch (device globals: no allocation allowed) ----------------
__device__ float g_x   [ROWS*DMODEL];
__device__ float g_xn  [ROWS*DMODEL];
__device__ float g_xp  [ROWS*D2V];
__device__ float g_bhat[(size_t)BATCH*K3*D2V];
__device__ float g_xca [ROWS*D2V];
__device__ float g_xco [ROWS*D2V];
__device__ float g_dl  [ROWS*D2V];
__device__ float g_xr  [ROWS*D2V];
__device__ float g_rowsum[ROWS];
__device__ float g_rowsq [ROWS];
__device__ float g_mu  [BATCH];
__device__ float g_rsig[BATCH];
__device__ float g_s   [ROWS];

__device__ __forceinline__ float siluf(float v){ return v / (1.f + expf(-v)); }
__device__ __forceinline__ float softplusf(float v){ return (v > 20.f) ? v : log1pf(expf(v)); }

// ---------------- stage 1: embedding gather + per-row sum/sumsq ----------------
__global__ void k_embed(const int* __restrict__ ids, const float* __restrict__ emb)
{
    int row = blockIdx.x;
    int id  = ids[row];
    const float* src = emb + (size_t)id * DMODEL;
    float s = 0.f, ss = 0.f;
    for (int d = threadIdx.x; d < DMODEL; d += blockDim.x) {
        float v = __ldg(src + d);
        g_x[(size_t)row * DMODEL + d] = v;
        s += v; ss += v * v;
    }
    __shared__ float sh[64];
    int lane = threadIdx.x & 31, w = threadIdx.x >> 5;
    #pragma unroll
    for (int o = 16; o; o >>= 1) {
        s  += __shfl_down_sync(0xffffffffu, s,  o);
        ss += __shfl_down_sync(0xffffffffu, ss, o);
    }
    if (!lane) { sh[w] = s; sh[32 + w] = ss; }
    __syncthreads();
    if (threadIdx.x == 0) {
        float S = 0.f, SS = 0.f;
        int nw = blockDim.x >> 5;
        for (int i = 0; i < nw; i++) { S += sh[i]; SS += sh[32 + i]; }
        g_rowsum[row] = S; g_rowsq[row] = SS;
    }
}

// ---------------- stage 2: per-sample mean / rsqrt(var) ----------------
__global__ void k_samplestats()
{
    int b = blockIdx.x;
    float s = 0.f, ss = 0.f;
    for (int r = threadIdx.x; r < LSEQ; r += blockDim.x) {
        s += g_rowsum[b * LSEQ + r]; ss += g_rowsq[b * LSEQ + r];
    }
    __shared__ float sh[64];
    int lane = threadIdx.x & 31, w = threadIdx.x >> 5;
    #pragma unroll
    for (int o = 16; o; o >>= 1) {
        s  += __shfl_down_sync(0xffffffffu, s,  o);
        ss += __shfl_down_sync(0xffffffffu, ss, o);
    }
    if (!lane) { sh[w] = s; sh[32 + w] = ss; }
    __syncthreads();
    if (threadIdx.x == 0) {
        float S = 0.f, SS = 0.f;
        int nw = blockDim.x >> 5;
        for (int i = 0; i < nw; i++) { S += sh[i]; SS += sh[32 + i]; }
        float inv = 1.f / ((float)LSEQ * (float)DMODEL);
        float mu  = S * inv;
        float var = SS * inv - mu * mu;
        g_mu[b]   = mu;
        g_rsig[b] = rsqrtf(var + 1e-5f);
    }
}

// ---------------- stage 3: apply LN + RMSNorm (analytic per-row scale) ----------------
__global__ void k_norm(const float* __restrict__ rms_w)
{
    int row = blockIdx.x;
    int b = row >> 10;
    float mu = g_mu[b], rs = g_rsig[b];
    // mean_d(((x-mu)*rs)^2) from row sums
    float msq = rs * rs * (g_rowsq[row] - 2.f * mu * g_rowsum[row] + (float)DMODEL * mu * mu) / (float)DMODEL;
    float rr  = rsqrtf(msq + 1e-5f);
    float a   = rs * rr;
    const float* xr = g_x  + (size_t)row * DMODEL;
    float*       xo = g_xn + (size_t)row * DMODEL;
    for (int d = threadIdx.x; d < DMODEL; d += blockDim.x)
        xo[d] = (xr[d] - mu) * a * rms_w[d];
}

// ---------------- generic tiled SGEMM, 128x128x16, 8x8/thread ----------------
// C = epi(A@B + biasN[col] + biasM[row]); all dims multiples of tile sizes (checked on host).
template<int EPI>  // 0 = none, 1 = silu, 2 = softplus
__global__ void __launch_bounds__(256, 2) k_sgemm(
    const float* __restrict__ A, const float* __restrict__ B,
    const float* __restrict__ biasN, const float* __restrict__ biasM,
    float* __restrict__ C, int M, int N, int K,
    long sA, long sB, long sC)
{
    A += (size_t)blockIdx.z * sA;
    B += (size_t)blockIdx.z * sB;
    C += (size_t)blockIdx.z * sC;

    __shared__ float As[16][128];
    __shared__ float Bs[16][128];

    const int tid  = threadIdx.x;
    const int row0 = blockIdx.y * 128;
    const int col0 = blockIdx.x * 128;
    const int tr = (tid >> 4) << 3;   // 0..120
    const int tc = (tid & 15) << 3;   // 0..120

    float acc[8][8];
    #pragma unroll
    for (int i = 0; i < 8; i++)
        #pragma unroll
        for (int j = 0; j < 8; j++) acc[i][j] = 0.f;

    for (int k0 = 0; k0 < K; k0 += 16) {
        #pragma unroll
        for (int it = 0; it < 2; it++) {
            int idx = tid + it * 256;
            int ar = idx >> 2, ak = (idx & 3) << 2;
            float4 va = *(const float4*)(A + (size_t)(row0 + ar) * K + k0 + ak);
            As[ak + 0][ar] = va.x; As[ak + 1][ar] = va.y;
            As[ak + 2][ar] = va.z; As[ak + 3][ar] = va.w;
            int br = idx >> 5, bc = (idx & 31) << 2;
            *(float4*)(&Bs[br][bc]) = *(const float4*)(B + (size_t)(k0 + br) * N + col0 + bc);
        }
        __syncthreads();
        #pragma unroll
        for (int k = 0; k < 16; k++) {
            float ra[8], rb[8];
            #pragma unroll
            for (int i = 0; i < 8; i++) ra[i] = As[k][tr + i];
            #pragma unroll
            for (int j = 0; j < 8; j++) rb[j] = Bs[k][tc + j];
            #pragma unroll
            for (int i = 0; i < 8; i++)
                #pragma unroll
                for (int j = 0; j < 8; j++)
                    acc[i][j] += ra[i] * rb[j];
        }
        __syncthreads();
    }

    float bn[8];
    #pragma unroll
    for (int j = 0; j < 8; j++) bn[j] = biasN ? biasN[col0 + tc + j] : 0.f;

    #pragma unroll
    for (int i = 0; i < 8; i++) {
        int r = row0 + tr + i;
        float bm = biasM ? biasM[r] : 0.f;
        #pragma unroll
        for (int j = 0; j < 8; j++) {
            float v = acc[i][j] + bn[j] + bm;
            if (EPI == 1) v = siluf(v);
            else if (EPI == 2) v = softplusf(v);
            acc[i][j] = v;
        }
        *(float4*)(C + (size_t)r * N + col0 + tc)     = make_float4(acc[i][0], acc[i][1], acc[i][2], acc[i][3]);
        *(float4*)(C + (size_t)r * N + col0 + tc + 4) = make_float4(acc[i][4], acc[i][5], acc[i][6], acc[i][7]);
    }
}

// ---------------- build shifted conv operand: Bhat[b][3i+k][t] = xp[b][i][t+k-1] ----------------
__global__ void k_bhat()
{
    size_t idx = (size_t)blockIdx.x * blockDim.x + threadIdx.x;  // < BATCH*K3*D2V
    int t  = (int)(idx % D2V);
    int ik = (int)((idx / D2V) % K3);
    int b  = (int)(idx / ((size_t)D2V * K3));
    int i = ik / 3, k = ik % 3;
    int ts = t + k - 1;
    float v = (ts >= 0 && ts < D2V) ? g_xp[((size_t)b * LSEQ + i) * D2V + ts] : 0.f;
    g_bhat[idx] = v;
}

// ---------------- per-row s = sum_n (xco@fc2+b2)_n * (xco@fc3+b3)_n ----------------
__global__ void k_bcs(const float* __restrict__ w2, const float* __restrict__ b2,
                      const float* __restrict__ w3, const float* __restrict__ b3)
{
    int row = blockIdx.x;
    const float* xr = g_xco + (size_t)row * D2V;
    float ab[NSTATE], ac[NSTATE];
    #pragma unroll
    for (int n = 0; n < NSTATE; n++) { ab[n] = 0.f; ac[n] = 0.f; }

    for (int k = threadIdx.x; k < D2V; k += blockDim.x) {
        float xv = xr[k];
        const float4* q2 = (const float4*)(w2 + (size_t)k * NSTATE);
        const float4* q3 = (const float4*)(w3 + (size_t)k * NSTATE);
        #pragma unroll
        for (int q = 0; q < 4; q++) {
            float4 a = q2[q], c = q3[q];
            ab[4*q+0] += xv * a.x; ab[4*q+1] += xv * a.y; ab[4*q+2] += xv * a.z; ab[4*q+3] += xv * a.w;
            ac[4*q+0] += xv * c.x; ac[4*q+1] += xv * c.y; ac[4*q+2] += xv * c.z; ac[4*q+3] += xv * c.w;
        }
    }
    __shared__ float shb[NSTATE], shc[NSTATE];
    if (threadIdx.x < NSTATE) { shb[threadIdx.x] = 0.f; shc[threadIdx.x] = 0.f; }
    __syncthreads();
    int lane = threadIdx.x & 31;
    #pragma unroll
    for (int n = 0; n < NSTATE; n++) {
        float vb = ab[n], vc = ac[n];
        #pragma unroll
        for (int o = 16; o; o >>= 1) {
            vb += __shfl_down_sync(0xffffffffu, vb, o);
            vc += __shfl_down_sync(0xffffffffu, vc, o);
        }
        if (lane == 0) { atomicAdd(&shb[n], vb); atomicAdd(&shc[n], vc); }
    }
    __syncthreads();
    if (threadIdx.x == 0) {
        float s = 0.f;
        #pragma unroll
        for (int n = 0; n < NSTATE; n++) s += (shb[n] + b2[n]) * (shc[n] + b3[n]);
        g_s[row] = s;
    }
}

// ---------------- prod = silu(xco*delta*s) * x_res  (into g_xca, reuse) ----------------
__global__ void k_prod()
{
    size_t i4 = (size_t)blockIdx.x * blockDim.x + threadIdx.x;   // < ROWS*D2V/4
    int row = (int)(i4 / (D2V / 4));
    float sv = g_s[row];
    float4 xo = ((const float4*)g_xco)[i4];
    float4 dl = ((const float4*)g_dl )[i4];
    float4 xr = ((const float4*)g_xr )[i4];
    float4 r;
    r.x = siluf(xo.x * dl.x * sv) * xr.x;
    r.y = siluf(xo.y * dl.y * sv) * xr.y;
    r.z = siluf(xo.z * dl.z * sv) * xr.z;
    r.w = siluf(xo.w * dl.w * sv) * xr.w;
    ((float4*)g_xca)[i4] = r;
}

// ---------------- pooled = max over seq axis of out ----------------
__global__ void k_maxpool(const float* __restrict__ out, float* __restrict__ pooled)
{
    int b = blockIdx.y;
    int d = blockIdx.x * blockDim.x + threadIdx.x;
    if (d >= DMODEL) return;
    const float* p = out + (size_t)b * LSEQ * DMODEL + d;
    float m0 = -FLT_MAX, m1 = -FLT_MAX, m2 = -FLT_MAX, m3 = -FLT_MAX;
    for (int l = 0; l < LSEQ; l += 4) {
        m0 = fmaxf(m0, p[(size_t)(l + 0) * DMODEL]);
        m1 = fmaxf(m1, p[(size_t)(l + 1) * DMODEL]);
        m2 = fmaxf(m2, p[(size_t)(l + 2) * DMODEL]);
        m3 = fmaxf(m3, p[(size_t)(l + 3) * DMODEL]);
    }
    pooled[b * DMODEL + d] = fmaxf(fmaxf(m0, m1), fmaxf(m2, m3));
}

// ---------------- launch ----------------
extern "C" void kernel_launch(void* const* d_in, const int* in_sizes, int n_in,
                              void* d_out, int out_size)
{
    const int*   ids    = (const int*)  d_in[0];
    const float* emb    = (const float*)d_in[1];
    const float* rms_w  = (const float*)d_in[2];
    const float* W_in   = (const float*)d_in[3];
    const float* b_in   = (const float*)d_in[4];
    const float* conv_w = (const float*)d_in[5];
    const float* conv_b = (const float*)d_in[6];
    const float* W_cl   = (const float*)d_in[7];
    const float* b_cl   = (const float*)d_in[8];
    const float* fc1_w  = (const float*)d_in[9];
    const float* fc1_b  = (const float*)d_in[10];
    const float* fc2_w  = (const float*)d_in[11];
    const float* fc2_b  = (const float*)d_in[12];
    const float* fc3_w  = (const float*)d_in[13];
    const float* fc3_b  = (const float*)d_in[14];
    /* d_in[15] = A : provably unused (zero-init state) */
    const float* W_D    = (const float*)d_in[16];
    const float* b_D    = (const float*)d_in[17];
    const float* W_out  = (const float*)d_in[18];
    const float* b_out  = (const float*)d_in[19];
    float* out = (float*)d_out;

    float *px, *pxn, *pxp, *pbh, *pxca, *pxco, *pdl, *pxr;
    cudaGetSymbolAddress((void**)&px,   g_x);
    cudaGetSymbolAddress((void**)&pxn,  g_xn);
    cudaGetSymbolAddress((void**)&pxp,  g_xp);
    cudaGetSymbolAddress((void**)&pbh,  g_bhat);
    cudaGetSymbolAddress((void**)&pxca, g_xca);
    cudaGetSymbolAddress((void**)&pxco, g_xco);
    cudaGetSymbolAddress((void**)&pdl,  g_dl);
    cudaGetSymbolAddress((void**)&pxr,  g_xr);

    // 1-3: embed + LN + RMSNorm
    k_embed<<<ROWS, 256>>>(ids, emb);
    k_samplestats<<<BATCH, 256>>>();
    k_norm<<<ROWS, 256>>>(rms_w);

    // 4: xp = xn @ W_in + b_in          [8192,768]x[768,1536]
    k_sgemm<0><<<dim3(D2V/128, ROWS/128, 1), 256>>>(pxn, W_in, b_in, nullptr, pxp,
                                                    ROWS, D2V, DMODEL, 0, 0, 0);

    // 5: Bhat gather (shifted xp view for conv-as-GEMM)
    {
        size_t tot = (size_t)BATCH * K3 * D2V;
        k_bhat<<<(unsigned)(tot / 256), 256>>>();
    }

    // 6: xca = silu(conv_w[1024,3072] @ Bhat[b] + conv_b[row])   per batch
    k_sgemm<1><<<dim3(D2V/128, LSEQ/128, BATCH), 256>>>(conv_w, pbh, nullptr, conv_b, pxca,
                                                        LSEQ, D2V, K3,
                                                        0, (long)K3 * D2V, (long)LSEQ * D2V);

    // 7: xco = xca @ W_cl + b_cl        [8192,1536]x[1536,1536]
    k_sgemm<0><<<dim3(D2V/128, ROWS/128, 1), 256>>>(pxca, W_cl, b_cl, nullptr, pxco,
                                                    ROWS, D2V, D2V, 0, 0, 0);

    // 8: delta = softplus(xco @ fc1_w + fc1_b)
    k_sgemm<2><<<dim3(D2V/128, ROWS/128, 1), 256>>>(pxco, fc1_w, fc1_b, nullptr, pdl,
                                                    ROWS, D2V, D2V, 0, 0, 0);

    // 9: s[row] = sum_n Bm*Cm
    k_bcs<<<ROWS, 256>>>(fc2_w, fc2_b, fc3_w, fc3_b);

    // 10: x_res = silu(xn @ W_D + b_D)
    k_sgemm<1><<<dim3(D2V/128, ROWS/128, 1), 256>>>(pxn, W_D, b_D, nullptr, pxr,
                                                    ROWS, D2V, DMODEL, 0, 0, 0);

    // 11: prod = silu(xco*delta*s) * x_res   (into g_xca)
    k_prod<<<(ROWS * D2V / 4) / 256, 256>>>();

    // 12: out = prod @ W_out + b_out    [8192,1536]x[1536,768] -> d_out
    k_sgemm<0><<<dim3(DMODEL/128, ROWS/128, 1), 256>>>(pxca, W_out, b_out, nullptr, out,
                                                       ROWS, DMODEL, D2V, 0, 0, 0);

    // 13: pooled = max over seq (if harness expects it appended)
    if (out_size >= ROWS * DMODEL + BATCH * DMODEL)
        k_maxpool<<<dim3((DMODEL + 255) / 256, BATCH), 256>>>(out, out + (size_t)ROWS * DMODEL);
}

// round 2
// speedup vs baseline: 1.0547x; 1.0547x over previous
#include <cuda_runtime.h>
#include <math.h>
#include <float.h>

#define BATCH 8
#define LSEQ 1024
#define DMODEL 768
#define D2V 1536
#define NSTATE 16
#define ROWS (BATCH*LSEQ)     /* 8192 */
#define K3 (3*LSEQ)           /* 3072 */

// ---------------- scratch (device globals: no allocation allowed) ----------------
__device__ float g_x   [ROWS*DMODEL];
__device__ float g_xn  [ROWS*DMODEL];
__device__ float g_xp  [ROWS*D2V];
__device__ float g_bhat[(size_t)BATCH*K3*D2V];
__device__ float g_xca [ROWS*D2V];
__device__ float g_xco [ROWS*D2V];
__device__ float g_dl  [ROWS*D2V];
__device__ float g_xr  [ROWS*D2V];
__device__ float g_rowsum[ROWS];
__device__ float g_rowsq [ROWS];
__device__ float g_mu  [BATCH];
__device__ float g_rsig[BATCH];
__device__ float g_s   [ROWS];

__device__ __forceinline__ float siluf(float v){ return v / (1.f + expf(-v)); }
__device__ __forceinline__ float softplusf(float v){ return (v > 20.f) ? v : log1pf(expf(v)); }

// ---------------- stage 1: embedding gather + per-row sum/sumsq ----------------
__global__ void k_embed(const int* __restrict__ ids, const float* __restrict__ emb)
{
    int row = blockIdx.x;
    int id  = ids[row];
    const float* src = emb + (size_t)id * DMODEL;
    float s = 0.f, ss = 0.f;
    for (int d = threadIdx.x; d < DMODEL; d += blockDim.x) {
        float v = __ldg(src + d);
        g_x[(size_t)row * DMODEL + d] = v;
        s += v; ss += v * v;
    }
    __shared__ float sh[64];
    int lane = threadIdx.x & 31, w = threadIdx.x >> 5;
    #pragma unroll
    for (int o = 16; o; o >>= 1) {
        s  += __shfl_down_sync(0xffffffffu, s,  o);
        ss += __shfl_down_sync(0xffffffffu, ss, o);
    }
    if (!lane) { sh[w] = s; sh[32 + w] = ss; }
    __syncthreads();
    if (threadIdx.x == 0) {
        float S = 0.f, SS = 0.f;
        int nw = blockDim.x >> 5;
        for (int i = 0; i < nw; i++) { S += sh[i]; SS += sh[32 + i]; }
        g_rowsum[row] = S; g_rowsq[row] = SS;
    }
}

// ---------------- stage 2: per-sample mean / rsqrt(var) ----------------
__global__ void k_samplestats()
{
    int b = blockIdx.x;
    float s = 0.f, ss = 0.f;
    for (int r = threadIdx.x; r < LSEQ; r += blockDim.x) {
        s += g_rowsum[b * LSEQ + r]; ss += g_rowsq[b * LSEQ + r];
    }
    __shared__ float sh[64];
    int lane = threadIdx.x & 31, w = threadIdx.x >> 5;
    #pragma unroll
    for (int o = 16; o; o >>= 1) {
        s  += __shfl_down_sync(0xffffffffu, s,  o);
        ss += __shfl_down_sync(0xffffffffu, ss, o);
    }
    if (!lane) { sh[w] = s; sh[32 + w] = ss; }
    __syncthreads();
    if (threadIdx.x == 0) {
        float S = 0.f, SS = 0.f;
        int nw = blockDim.x >> 5;
        for (int i = 0; i < nw; i++) { S += sh[i]; SS += sh[32 + i]; }
        float inv = 1.f / ((float)LSEQ * (float)DMODEL);
        float mu  = S * inv;
        float var = SS * inv - mu * mu;
        g_mu[b]   = mu;
        g_rsig[b] = rsqrtf(var + 1e-5f);
    }
}

// ---------------- stage 3: apply LN + RMSNorm (analytic per-row scale) ----------------
__global__ void k_norm(const float* __restrict__ rms_w)
{
    int row = blockIdx.x;
    int b = row >> 10;
    float mu = g_mu[b], rs = g_rsig[b];
    // mean_d(((x-mu)*rs)^2) from row sums
    float msq = rs * rs * (g_rowsq[row] - 2.f * mu * g_rowsum[row] + (float)DMODEL * mu * mu) / (float)DMODEL;
    float rr  = rsqrtf(msq + 1e-5f);
    float a   = rs * rr;
    const float* xr = g_x  + (size_t)row * DMODEL;
    float*       xo = g_xn + (size_t)row * DMODEL;
    for (int d = threadIdx.x; d < DMODEL; d += blockDim.x)
        xo[d] = (xr[d] - mu) * a * rms_w[d];
}

// ---------------- generic tiled SGEMM, 128x128x16, 8x8/thread ----------------
// C = epi(A@B + biasN[col] + biasM[row]); all dims multiples of tile sizes (checked on host).
template<int EPI>  // 0 = none, 1 = silu, 2 = softplus
__global__ void __launch_bounds__(256, 2) k_sgemm(
    const float* __restrict__ A, const float* __restrict__ B,
    const float* __restrict__ biasN, const float* __restrict__ biasM,
    float* __restrict__ C, int M, int N, int K,
    long sA, long sB, long sC)
{
    A += (size_t)blockIdx.z * sA;
    B += (size_t)blockIdx.z * sB;
    C += (size_t)blockIdx.z * sC;

    __shared__ float As[16][128];
    __shared__ float Bs[16][128];

    const int tid  = threadIdx.x;
    const int row0 = blockIdx.y * 128;
    const int col0 = blockIdx.x * 128;
    const int tr = (tid >> 4) << 3;   // 0..120
    const int tc = (tid & 15) << 3;   // 0..120

    float acc[8][8];
    #pragma unroll
    for (int i = 0; i < 8; i++)
        #pragma unroll
        for (int j = 0; j < 8; j++) acc[i][j] = 0.f;

    for (int k0 = 0; k0 < K; k0 += 16) {
        #pragma unroll
        for (int it = 0; it < 2; it++) {
            int idx = tid + it * 256;
            int ar = idx >> 2, ak = (idx & 3) << 2;
            float4 va = *(const float4*)(A + (size_t)(row0 + ar) * K + k0 + ak);
            As[ak + 0][ar] = va.x; As[ak + 1][ar] = va.y;
            As[ak + 2][ar] = va.z; As[ak + 3][ar] = va.w;
            int br = idx >> 5, bc = (idx & 31) << 2;
            *(float4*)(&Bs[br][bc]) = *(const float4*)(B + (size_t)(k0 + br) * N + col0 + bc);
        }
        __syncthreads();
        #pragma unroll
        for (int k = 0; k < 16; k++) {
            float ra[8], rb[8];
            #pragma unroll
            for (int i = 0; i < 8; i++) ra[i] = As[k][tr + i];
            #pragma unroll
            for (int j = 0; j < 8; j++) rb[j] = Bs[k][tc + j];
            #pragma unroll
            for (int i = 0; i < 8; i++)
                #pragma unroll
                for (int j = 0; j < 8; j++)
                    acc[i][j] += ra[i] * rb[j];
        }
        __syncthreads();
    }

    float bn[8];
    #pragma unroll
    for (int j = 0; j < 8; j++) bn[j] = biasN ? biasN[col0 + tc + j] : 0.f;

    #pragma unroll
    for (int i = 0; i < 8; i++) {
        int r = row0 + tr + i;
        float bm = biasM ? biasM[r] : 0.f;
        #pragma unroll
        for (int j = 0; j < 8; j++) {
            float v = acc[i][j] + bn[j] + bm;
            if (EPI == 1) v = siluf(v);
            else if (EPI == 2) v = softplusf(v);
            acc[i][j] = v;
        }
        *(float4*)(C + (size_t)r * N + col0 + tc)     = make_float4(acc[i][0], acc[i][1], acc[i][2], acc[i][3]);
        *(float4*)(C + (size_t)r * N + col0 + tc + 4) = make_float4(acc[i][4], acc[i][5], acc[i][6], acc[i][7]);
    }
}

// ---------------- build shifted conv operand: Bhat[b][3i+k][t] = xp[b][i][t+k-1] ----------------
__global__ void k_bhat()
{
    size_t idx = (size_t)blockIdx.x * blockDim.x + threadIdx.x;  // < BATCH*K3*D2V
    int t  = (int)(idx % D2V);
    int ik = (int)((idx / D2V) % K3);
    int b  = (int)(idx / ((size_t)D2V * K3));
    int i = ik / 3, k = ik % 3;
    int ts = t + k - 1;
    float v = (ts >= 0 && ts < D2V) ? g_xp[((size_t)b * LSEQ + i) * D2V + ts] : 0.f;
    g_bhat[idx] = v;
}

// ---------------- per-row s = sum_n (xco@fc2+b2)_n * (xco@fc3+b3)_n ----------------
__global__ void k_bcs(const float* __restrict__ w2, const float* __restrict__ b2,
                      const float* __restrict__ w3, const float* __restrict__ b3)
{
    int row = blockIdx.x;
    const float* xr = g_xco + (size_t)row * D2V;
    float ab[NSTATE], ac[NSTATE];
    #pragma unroll
    for (int n = 0; n < NSTATE; n++) { ab[n] = 0.f; ac[n] = 0.f; }

    for (int k = threadIdx.x; k < D2V; k += blockDim.x) {
        float xv = xr[k];
        const float4* q2 = (const float4*)(w2 + (size_t)k * NSTATE);
        const float4* q3 = (const float4*)(w3 + (size_t)k * NSTATE);
        #pragma unroll
        for (int q = 0; q < 4; q++) {
            float4 a = q2[q], c = q3[q];
            ab[4*q+0] += xv * a.x; ab[4*q+1] += xv * a.y; ab[4*q+2] += xv * a.z; ab[4*q+3] += xv * a.w;
            ac[4*q+0] += xv * c.x; ac[4*q+1] += xv * c.y; ac[4*q+2] += xv * c.z; ac[4*q+3] += xv * c.w;
        }
    }
    __shared__ float shb[NSTATE], shc[NSTATE];
    if (threadIdx.x < NSTATE) { shb[threadIdx.x] = 0.f; shc[threadIdx.x] = 0.f; }
    __syncthreads();
    int lane = threadIdx.x & 31;
    #pragma unroll
    for (int n = 0; n < NSTATE; n++) {
        float vb = ab[n], vc = ac[n];
        #pragma unroll
        for (int o = 16; o; o >>= 1) {
            vb += __shfl_down_sync(0xffffffffu, vb, o);
            vc += __shfl_down_sync(0xffffffffu, vc, o);
        }
        if (lane == 0) { atomicAdd(&shb[n], vb); atomicAdd(&shc[n], vc); }
    }
    __syncthreads();
    if (threadIdx.x == 0) {
        float s = 0.f;
        #pragma unroll
        for (int n = 0; n < NSTATE; n++) s += (shb[n] + b2[n]) * (shc[n] + b3[n]);
        g_s[row] = s;
    }
}

// ---------------- prod = silu(xco*delta*s) * x_res  (into g_xca, reuse) ----------------
__global__ void k_prod()
{
    size_t i4 = (size_t)blockIdx.x * blockDim.x + threadIdx.x;   // < ROWS*D2V/4
    int row = (int)(i4 / (D2V / 4));
    float sv = g_s[row];
    float4 xo = ((const float4*)g_xco)[i4];
    float4 dl = ((const float4*)g_dl )[i4];
    float4 xr = ((const float4*)g_xr )[i4];
    float4 r;
    r.x = siluf(xo.x * dl.x * sv) * xr.x;
    r.y = siluf(xo.y * dl.y * sv) * xr.y;
    r.z = siluf(xo.z * dl.z * sv) * xr.z;
    r.w = siluf(xo.w * dl.w * sv) * xr.w;
    ((float4*)g_xca)[i4] = r;
}

// ---------------- pooled = max over seq axis of out ----------------
__global__ void k_maxpool(const float* __restrict__ out, float* __restrict__ pooled)
{
    int b = blockIdx.y;
    int d = blockIdx.x * blockDim.x + threadIdx.x;
    if (d >= DMODEL) return;
    const float* p = out + (size_t)b * LSEQ * DMODEL + d;
    float m0 = -FLT_MAX, m1 = -FLT_MAX, m2 = -FLT_MAX, m3 = -FLT_MAX;
    for (int l = 0; l < LSEQ; l += 4) {
        m0 = fmaxf(m0, p[(size_t)(l + 0) * DMODEL]);
        m1 = fmaxf(m1, p[(size_t)(l + 1) * DMODEL]);
        m2 = fmaxf(m2, p[(size_t)(l + 2) * DMODEL]);
        m3 = fmaxf(m3, p[(size_t)(l + 3) * DMODEL]);
    }
    pooled[b * DMODEL + d] = fmaxf(fmaxf(m0, m1), fmaxf(m2, m3));
}

// ---------------- launch ----------------
extern "C" void kernel_launch(void* const* d_in, const int* in_sizes, int n_in,
                              void* d_out, int out_size)
{
    const int*   ids    = (const int*)  d_in[0];
    const float* emb    = (const float*)d_in[1];
    const float* rms_w  = (const float*)d_in[2];
    const float* W_in   = (const float*)d_in[3];
    const float* b_in   = (const float*)d_in[4];
    const float* conv_w = (const float*)d_in[5];
    const float* conv_b = (const float*)d_in[6];
    const float* W_cl   = (const float*)d_in[7];
    const float* b_cl   = (const float*)d_in[8];
    const float* fc1_w  = (const float*)d_in[9];
    const float* fc1_b  = (const float*)d_in[10];
    const float* fc2_w  = (const float*)d_in[11];
    const float* fc2_b  = (const float*)d_in[12];
    const float* fc3_w  = (const float*)d_in[13];
    const float* fc3_b  = (const float*)d_in[14];
    /* d_in[15] = A : provably unused (zero-init state) */
    const float* W_D    = (const float*)d_in[16];
    const float* b_D    = (const float*)d_in[17];
    const float* W_out  = (const float*)d_in[18];
    const float* b_out  = (const float*)d_in[19];
    float* out = (float*)d_out;

    float *px, *pxn, *pxp, *pbh, *pxca, *pxco, *pdl, *pxr;
    cudaGetSymbolAddress((void**)&px,   g_x);
    cudaGetSymbolAddress((void**)&pxn,  g_xn);
    cudaGetSymbolAddress((void**)&pxp,  g_xp);
    cudaGetSymbolAddress((void**)&pbh,  g_bhat);
    cudaGetSymbolAddress((void**)&pxca, g_xca);
    cudaGetSymbolAddress((void**)&pxco, g_xco);
    cudaGetSymbolAddress((void**)&pdl,  g_dl);
    cudaGetSymbolAddress((void**)&pxr,  g_xr);

    // 1-3: embed + LN + RMSNorm
    k_embed<<<ROWS, 256>>>(ids, emb);
    k_samplestats<<<BATCH, 256>>>();
    k_norm<<<ROWS, 256>>>(rms_w);

    // 4: xp = xn @ W_in + b_in          [8192,768]x[768,1536]
    k_sgemm<0><<<dim3(D2V/128, ROWS/128, 1), 256>>>(pxn, W_in, b_in, nullptr, pxp,
                                                    ROWS, D2V, DMODEL, 0, 0, 0);

    // 5: Bhat gather (shifted xp view for conv-as-GEMM)
    {
        size_t tot = (size_t)BATCH * K3 * D2V;
        k_bhat<<<(unsigned)(tot / 256), 256>>>();
    }

    // 6: xca = silu(conv_w[1024,3072] @ Bhat[b] + conv_b[row])   per batch
    k_sgemm<1><<<dim3(D2V/128, LSEQ/128, BATCH), 256>>>(conv_w, pbh, nullptr, conv_b, pxca,
                                                        LSEQ, D2V, K3,
                                                        0, (long)K3 * D2V, (long)LSEQ * D2V);

    // 7: xco = xca @ W_cl + b_cl        [8192,1536]x[1536,1536]
    k_sgemm<0><<<dim3(D2V/128, ROWS/128, 1), 256>>>(pxca, W_cl, b_cl, nullptr, pxco,
                                                    ROWS, D2V, D2V, 0, 0, 0);

    // 8: delta = softplus(xco @ fc1_w + fc1_b)
    k_sgemm<2><<<dim3(D2V/128, ROWS/128, 1), 256>>>(pxco, fc1_w, fc1_b, nullptr, pdl,
                                                    ROWS, D2V, D2V, 0, 0, 0);

    // 9: s[row] = sum_n Bm*Cm
    k_bcs<<<ROWS, 256>>>(fc2_w, fc2_b, fc3_w, fc3_b);

    // 10: x_res = silu(xn @ W_D + b_D)
    k_sgemm<1><<<dim3(D2V/128, ROWS/128, 1), 256>>>(pxn, W_D, b_D, nullptr, pxr,
                                                    ROWS, D2V, DMODEL, 0, 0, 0);

    // 11: prod = silu(xco*delta*s) * x_res   (into g_xca)
    k_prod<<<(ROWS * D2V / 4) / 256, 256>>>();

    // 12: out = prod @ W_out + b_out    [8192,1536]x[1536,768] -> d_out
    k_sgemm<0><<<dim3(DMODEL/128, ROWS/128, 1), 256>>>(pxca, W_out, b_out, nullptr, out,
                                                       ROWS, DMODEL, D2V, 0, 0, 0);

    // 13: pooled = max over seq (if harness expects it appended)
    if (out_size >= ROWS * DMODEL + BATCH * DMODEL)
        k_maxpool<<<dim3((DMODEL + 255) / 256, BATCH), 256>>>(out, out + (size_t)ROWS * DMODEL);
}

// round 4
// speedup vs baseline: 2.8461x; 2.6986x over previous
#include <cuda_runtime.h>
#include <cuda_bf16.h>
#include <math.h>
#include <float.h>
#include <stdint.h>

#define BATCH 8
#define LSEQ 1024
#define DMODEL 768
#define D2V 1536
#define NSTATE 16
#define ROWS (BATCH*LSEQ)
#define K3 (3*LSEQ)

#define BM 128
#define BN 128
#define BK 64
#define STAGES 3
#define STAGE_BYTES 65536u
#define SMEM_DYN (STAGES*STAGE_BYTES)

typedef __nv_bfloat16 bf16;

// ------------------------- device scratch -------------------------
__device__ float g_x   [ROWS*DMODEL];
__device__ float g_xp  [ROWS*D2V];
__device__ float g_xco [ROWS*D2V];
__device__ float g_dl  [ROWS*D2V];
__device__ float g_xr  [ROWS*D2V];
__device__ float g_rowsum[ROWS];
__device__ float g_rowsq [ROWS];
__device__ float g_mu  [BATCH];
__device__ float g_rsig[BATCH];
__device__ float g_s   [ROWS];

__device__ bf16 g_xnP_h [ROWS*DMODEL], g_xnP_l [ROWS*DMODEL];
__device__ bf16 g_xcaP_h[ROWS*D2V],    g_xcaP_l[ROWS*D2V];
__device__ bf16 g_xcoP_h[ROWS*D2V],    g_xcoP_l[ROWS*D2V];
__device__ bf16 g_prP_h [ROWS*D2V],    g_prP_l [ROWS*D2V];
// weights kept in natural [K][N] layout, split hi/lo
__device__ bf16 g_WinS_h[DMODEL*D2V],  g_WinS_l[DMODEL*D2V];
__device__ bf16 g_WclS_h[D2V*D2V],     g_WclS_l[D2V*D2V];
__device__ bf16 g_fc1S_h[D2V*D2V],     g_fc1S_l[D2V*D2V];
__device__ bf16 g_WDS_h [DMODEL*D2V],  g_WDS_l [DMODEL*D2V];
__device__ bf16 g_WoS_h [D2V*DMODEL],  g_WoS_l [D2V*DMODEL];
// conv operands: A = [o][kidx] (kidx = k*1024+i), B = [b][kidx][t]
__device__ bf16 g_cA_h  [LSEQ*K3],     g_cA_l  [LSEQ*K3];
__device__ bf16 g_cB_h  [(size_t)BATCH*K3*D2V];
__device__ bf16 g_cB_l  [(size_t)BATCH*K3*D2V];

// ------------------------- helpers -------------------------
__device__ __forceinline__ float siluf(float v){ return v / (1.f + expf(-v)); }
__device__ __forceinline__ float softplusf(float v){ return (v > 20.f) ? v : log1pf(expf(v)); }

__device__ __forceinline__ uint32_t smem_u32(const void* p){
    uint32_t a;
    asm("{ .reg .u64 t; cvta.to.shared.u64 t, %1; cvt.u32.u64 %0, t; }" : "=r"(a) : "l"(p));
    return a;
}
__device__ __forceinline__ void cpa16(uint32_t dst, const void* src){
    asm volatile("cp.async.cg.shared.global [%0], [%1], 16;" :: "r"(dst), "l"(src) : "memory");
}
#define CP_COMMIT() asm volatile("cp.async.commit_group;" ::: "memory")
#define CP_WAIT(n)  asm volatile("cp.async.wait_group %0;" :: "n"(n) : "memory")

__device__ __forceinline__ void ldsm4(uint32_t addr, uint32_t* r){
    asm volatile("ldmatrix.sync.aligned.m8n8.x4.shared.b16 {%0,%1,%2,%3}, [%4];"
        : "=r"(r[0]), "=r"(r[1]), "=r"(r[2]), "=r"(r[3]) : "r"(addr));
}
__device__ __forceinline__ void ldsm4t(uint32_t addr, uint32_t* r0, uint32_t* r1){
    asm volatile("ldmatrix.sync.aligned.m8n8.x4.trans.shared.b16 {%0,%1,%2,%3}, [%4];"
        : "=r"(r0[0]), "=r"(r0[1]), "=r"(r1[0]), "=r"(r1[1]) : "r"(addr));
}
__device__ __forceinline__ void mma16816(float* d, const uint32_t* a, const uint32_t* b){
    asm volatile("mma.sync.aligned.m16n8k16.row.col.f32.bf16.bf16.f32 "
        "{%0,%1,%2,%3}, {%4,%5,%6,%7}, {%8,%9}, {%0,%1,%2,%3};"
        : "+f"(d[0]), "+f"(d[1]), "+f"(d[2]), "+f"(d[3])
        : "r"(a[0]), "r"(a[1]), "r"(a[2]), "r"(a[3]), "r"(b[0]), "r"(b[1]));
}
__device__ __forceinline__ void splitf(float v, bf16& h, bf16& l){
    h = __float2bfloat16(v);
    l = __float2bfloat16(v - __bfloat162float(h));
}

// ------------------------- HMMA GEMM -------------------------
// C[M,N] = EPI(A[M,K] @ B[K,N] + biasN[n] + biasM[m]); A,B bf16 hi/lo.
// A rows m (stride K), B rows k (stride N). grid = (N/BN, M/BM, Z).
template<int EPI, bool SPLIT>
__global__ void __launch_bounds__(256, 1) k_tc(
    const bf16* __restrict__ Ah, const bf16* __restrict__ Al,
    const bf16* __restrict__ Bh, const bf16* __restrict__ Bl,
    const float* __restrict__ biasN, const float* __restrict__ biasM,
    float* __restrict__ C, bf16* __restrict__ Ch, bf16* __restrict__ Cl,
    int K, int N, long sA, long sB, long sC)
{
    extern __shared__ char smem[];
    const int tid  = threadIdx.x;
    const int wid  = tid >> 5, lane = tid & 31;
    const int wm   = wid & 3,  wn = wid >> 2;       // warp tile: rows wm*32, cols wn*64
    const int row0 = blockIdx.y * BM;
    const int col0 = blockIdx.x * BN;
    Ah += (size_t)blockIdx.z * sA;  Al += (size_t)blockIdx.z * sA;
    Bh += (size_t)blockIdx.z * sB;  Bl += (size_t)blockIdx.z * sB;
    if (C) C += (size_t)blockIdx.z * sC;
    if (SPLIT){ Ch += (size_t)blockIdx.z * sC; Cl += (size_t)blockIdx.z * sC; }
    const int NK = K >> 6;
    const uint32_t sbase = smem_u32(smem);

    float acc[2][8][4];
    #pragma unroll
    for (int mi = 0; mi < 2; mi++)
        #pragma unroll
        for (int nj = 0; nj < 8; nj++)
            #pragma unroll
            for (int q = 0; q < 4; q++) acc[mi][nj][q] = 0.f;

    // ---- stage fill: A 128x64 (h,l) rows of 128B/8 units; B 64x128 (h,l) rows of 256B/16 units
    auto fill = [&](int kc, int s){
        uint32_t st = sbase + (uint32_t)s * STAGE_BYTES;
        const bf16* ap[2] = { Ah, Al };
        #pragma unroll
        for (int arr = 0; arr < 2; arr++){
            uint32_t base = st + arr * 16384u;
            #pragma unroll
            for (int it = 0; it < 4; it++){
                int id = tid + it * 256;
                int r = id >> 3, u = id & 7;
                cpa16(base + r * 128 + (((uint32_t)(u ^ (r & 7))) << 4),
                      ap[arr] + (size_t)(row0 + r) * K + kc * 64 + u * 8);
            }
        }
        const bf16* bp[2] = { Bh, Bl };
        #pragma unroll
        for (int arr = 0; arr < 2; arr++){
            uint32_t base = st + 32768u + arr * 16384u;
            #pragma unroll
            for (int it = 0; it < 4; it++){
                int id = tid + it * 256;
                int k = id >> 4, u = id & 15;
                cpa16(base + k * 256 + (((uint32_t)(u ^ (k & 7))) << 4),
                      bp[arr] + (size_t)(kc * 64 + k) * N + col0 + u * 8);
            }
        }
        CP_COMMIT();
    };

    fill(0, 0);
    if (NK > 1) fill(1, 1); else CP_COMMIT();

    for (int kc = 0; kc < NK; kc++){
        int s = kc % STAGES;
        CP_WAIT(1);
        __syncthreads();

        uint32_t aAh = sbase + (uint32_t)s * STAGE_BYTES;
        uint32_t aAl = aAh + 16384u;
        uint32_t aBh = aAh + 32768u;
        uint32_t aBl = aAh + 49152u;

        #pragma unroll
        for (int ks = 0; ks < 4; ks++){
            uint32_t ah[2][4], al[2][4], bb[8][2];
            // A fragments (hi & lo)
            const int arow = wm * 32 + (lane & 15);
            const int au   = 2 * ks + (lane >> 4);
            #pragma unroll
            for (int mi = 0; mi < 2; mi++){
                int r = arow + mi * 16;
                uint32_t off = r * 128 + (((uint32_t)(au ^ (r & 7))) << 4);
                ldsm4(aAh + off, ah[mi]);
                ldsm4(aAl + off, al[mi]);
            }
            // B hi fragments
            const int bk = ks * 16 + (lane & 15);
            #pragma unroll
            for (int p = 0; p < 4; p++){
                int u = wn * 8 + p * 2 + (lane >> 4);
                uint32_t off = bk * 256 + (((uint32_t)(u ^ (bk & 7))) << 4);
                ldsm4t(aBh + off, bb[2*p], bb[2*p+1]);
            }
            // pass hh + lh
            #pragma unroll
            for (int mi = 0; mi < 2; mi++)
                #pragma unroll
                for (int nj = 0; nj < 8; nj++)
                    mma16816(acc[mi][nj], ah[mi], bb[nj]);
            #pragma unroll
            for (int mi = 0; mi < 2; mi++)
                #pragma unroll
                for (int nj = 0; nj < 8; nj++)
                    mma16816(acc[mi][nj], al[mi], bb[nj]);
            // B lo fragments (reuse regs), pass hl
            #pragma unroll
            for (int p = 0; p < 4; p++){
                int u = wn * 8 + p * 2 + (lane >> 4);
                uint32_t off = bk * 256 + (((uint32_t)(u ^ (bk & 7))) << 4);
                ldsm4t(aBl + off, bb[2*p], bb[2*p+1]);
            }
            #pragma unroll
            for (int mi = 0; mi < 2; mi++)
                #pragma unroll
                for (int nj = 0; nj < 8; nj++)
                    mma16816(acc[mi][nj], ah[mi], bb[nj]);
        }

        if (kc + 2 < NK) fill(kc + 2, (kc + 2) % STAGES);
        else CP_COMMIT();
    }

    // ---- epilogue: acc -> smem (padded) -> global
    __syncthreads();
    float* sf = (float*)smem;
    {
        const int mrow = wm * 32 + (lane >> 2);
        const int ncol = wn * 64 + (lane & 3) * 2;
        #pragma unroll
        for (int mi = 0; mi < 2; mi++)
            #pragma unroll
            for (int nj = 0; nj < 8; nj++){
                int m = mrow + mi * 16, n = ncol + nj * 8;
                float2 v0 = make_float2(acc[mi][nj][0], acc[mi][nj][1]);
                float2 v1 = make_float2(acc[mi][nj][2], acc[mi][nj][3]);
                *(float2*)&sf[(size_t)m * 132 + n]       = v0;
                *(float2*)&sf[(size_t)(m + 8) * 132 + n] = v1;
            }
    }
    __syncthreads();

    for (int i = tid; i < BM * (BN / 4); i += 256){
        int r = i >> 5, c = (i & 31) * 4;
        float4 v = *(float4*)&sf[(size_t)r * 132 + c];
        float bm = biasM ? __ldg(biasM + row0 + r) : 0.f;
        float vv[4] = { v.x, v.y, v.z, v.w };
        #pragma unroll
        for (int j = 0; j < 4; j++){
            float t = vv[j] + bm + (biasN ? __ldg(biasN + col0 + c + j) : 0.f);
            if (EPI == 1) t = siluf(t);
            else if (EPI == 2) t = softplusf(t);
            vv[j] = t;
        }
        size_t o = (size_t)(row0 + r) * N + col0 + c;
        if (C) *(float4*)(C + o) = make_float4(vv[0], vv[1], vv[2], vv[3]);
        if (SPLIT){
            bf16 hh[4], ll[4];
            #pragma unroll
            for (int j = 0; j < 4; j++) splitf(vv[j], hh[j], ll[j]);
            *(uint2*)(Ch + o) = *(uint2*)hh;
            *(uint2*)(Cl + o) = *(uint2*)ll;
        }
    }
}

// ------------------------- aux kernels -------------------------
__global__ void k_embed(const int* __restrict__ ids, const float* __restrict__ emb)
{
    int row = blockIdx.x;
    int id  = ids[row];
    const float* src = emb + (size_t)id * DMODEL;
    float s = 0.f, ss = 0.f;
    for (int d = threadIdx.x; d < DMODEL; d += blockDim.x){
        float v = __ldg(src + d);
        g_x[(size_t)row * DMODEL + d] = v;
        s += v; ss += v * v;
    }
    __shared__ float sh[64];
    int lane = threadIdx.x & 31, w = threadIdx.x >> 5;
    #pragma unroll
    for (int o = 16; o; o >>= 1){
        s  += __shfl_down_sync(0xffffffffu, s,  o);
        ss += __shfl_down_sync(0xffffffffu, ss, o);
    }
    if (!lane){ sh[w] = s; sh[32 + w] = ss; }
    __syncthreads();
    if (threadIdx.x == 0){
        float S = 0.f, SS = 0.f;
        int nw = blockDim.x >> 5;
        for (int i = 0; i < nw; i++){ S += sh[i]; SS += sh[32 + i]; }
        g_rowsum[row] = S; g_rowsq[row] = SS;
    }
}

__global__ void k_samplestats()
{
    int b = blockIdx.x;
    float s = 0.f, ss = 0.f;
    for (int r = threadIdx.x; r < LSEQ; r += blockDim.x){
        s += g_rowsum[b * LSEQ + r]; ss += g_rowsq[b * LSEQ + r];
    }
    __shared__ float sh[64];
    int lane = threadIdx.x & 31, w = threadIdx.x >> 5;
    #pragma unroll
    for (int o = 16; o; o >>= 1){
        s  += __shfl_down_sync(0xffffffffu, s,  o);
        ss += __shfl_down_sync(0xffffffffu, ss, o);
    }
    if (!lane){ sh[w] = s; sh[32 + w] = ss; }
    __syncthreads();
    if (threadIdx.x == 0){
        float S = 0.f, SS = 0.f;
        int nw = blockDim.x >> 5;
        for (int i = 0; i < nw; i++){ S += sh[i]; SS += sh[32 + i]; }
        float inv = 1.f / ((float)LSEQ * (float)DMODEL);
        float mu  = S * inv;
        float var = SS * inv - mu * mu;
        g_mu[b]   = mu;
        g_rsig[b] = rsqrtf(var + 1e-5f);
    }
}

__global__ void k_norm(const float* __restrict__ rms_w)
{
    int row = blockIdx.x;
    int b = row >> 10;
    float mu = g_mu[b], rs = g_rsig[b];
    float msq = rs * rs * (g_rowsq[row] - 2.f * mu * g_rowsum[row] + (float)DMODEL * mu * mu) / (float)DMODEL;
    float a = rs * rsqrtf(msq + 1e-5f);
    const float* xr = g_x + (size_t)row * DMODEL;
    for (int d = threadIdx.x; d < DMODEL; d += blockDim.x){
        float v = (xr[d] - mu) * a * rms_w[d];
        bf16 h, l; splitf(v, h, l);
        g_xnP_h[(size_t)row * DMODEL + d] = h;
        g_xnP_l[(size_t)row * DMODEL + d] = l;
    }
}

// pure split, natural [K][N] layout (no transpose)
__global__ void k_wsplit(const float* __restrict__ W, bf16* __restrict__ Wh, bf16* __restrict__ Wl)
{
    size_t i4 = (size_t)blockIdx.x * blockDim.x + threadIdx.x;
    float4 v = ((const float4*)W)[i4];
    bf16 hh[4], ll[4];
    splitf(v.x, hh[0], ll[0]); splitf(v.y, hh[1], ll[1]);
    splitf(v.z, hh[2], ll[2]); splitf(v.w, hh[3], ll[3]);
    *(uint2*)(Wh + i4 * 4) = *(uint2*)hh;
    *(uint2*)(Wl + i4 * 4) = *(uint2*)ll;
}

// conv A repack: cA[o][k*1024+i] = conv_w[o][3i+k]
__global__ void k_convA(const float* __restrict__ cw)
{
    int o = blockIdx.y;
    int i = blockIdx.x * 256 + threadIdx.x;
    #pragma unroll
    for (int k = 0; k < 3; k++){
        float v = cw[(size_t)o * K3 + 3 * i + k];
        bf16 h, l; splitf(v, h, l);
        size_t off = (size_t)o * K3 + k * 1024 + i;
        g_cA_h[off] = h; g_cA_l[off] = l;
    }
}

// conv B gather (k-major, no transpose): cB[b][k*1024+i][t] = xp[b][i][t+k-1]
__global__ void k_convB()
{
    int t = blockIdx.x * 256 + threadIdx.x;
    int i = blockIdx.y;
    int zk = blockIdx.z;
    int b = zk / 3, k = zk % 3;
    int ts = t + k - 1;
    float v = (ts >= 0 && ts < D2V) ? g_xp[((size_t)(b * LSEQ) + i) * D2V + ts] : 0.f;
    bf16 h, l; splitf(v, h, l);
    size_t o = (size_t)b * K3 * D2V + (size_t)(k * 1024 + i) * D2V + t;
    g_cB_h[o] = h; g_cB_l[o] = l;
}

__global__ void k_bcs(const float* __restrict__ w2, const float* __restrict__ b2,
                      const float* __restrict__ w3, const float* __restrict__ b3)
{
    int row = blockIdx.x;
    const float* xr = g_xco + (size_t)row * D2V;
    float ab[NSTATE], ac[NSTATE];
    #pragma unroll
    for (int n = 0; n < NSTATE; n++){ ab[n] = 0.f; ac[n] = 0.f; }
    for (int k = threadIdx.x; k < D2V; k += blockDim.x){
        float xv = xr[k];
        const float4* q2 = (const float4*)(w2 + (size_t)k * NSTATE);
        const float4* q3 = (const float4*)(w3 + (size_t)k * NSTATE);
        #pragma unroll
        for (int q = 0; q < 4; q++){
            float4 a = q2[q], c = q3[q];
            ab[4*q+0] += xv*a.x; ab[4*q+1] += xv*a.y; ab[4*q+2] += xv*a.z; ab[4*q+3] += xv*a.w;
            ac[4*q+0] += xv*c.x; ac[4*q+1] += xv*c.y; ac[4*q+2] += xv*c.z; ac[4*q+3] += xv*c.w;
        }
    }
    __shared__ float shb[NSTATE], shc[NSTATE];
    if (threadIdx.x < NSTATE){ shb[threadIdx.x] = 0.f; shc[threadIdx.x] = 0.f; }
    __syncthreads();
    int lane = threadIdx.x & 31;
    #pragma unroll
    for (int n = 0; n < NSTATE; n++){
        float vb = ab[n], vc = ac[n];
        #pragma unroll
        for (int o = 16; o; o >>= 1){
            vb += __shfl_down_sync(0xffffffffu, vb, o);
            vc += __shfl_down_sync(0xffffffffu, vc, o);
        }
        if (lane == 0){ atomicAdd(&shb[n], vb); atomicAdd(&shc[n], vc); }
    }
    __syncthreads();
    if (threadIdx.x == 0){
        float s = 0.f;
        #pragma unroll
        for (int n = 0; n < NSTATE; n++) s += (shb[n] + b2[n]) * (shc[n] + b3[n]);
        g_s[row] = s;
    }
}

__global__ void k_prod()
{
    size_t i4 = (size_t)blockIdx.x * blockDim.x + threadIdx.x;
    int row = (int)(i4 / (D2V / 4));
    float sv = g_s[row];
    float4 xo = ((const float4*)g_xco)[i4];
    float4 dl = ((const float4*)g_dl )[i4];
    float4 xr = ((const float4*)g_xr )[i4];
    float r0 = siluf(xo.x*dl.x*sv) * xr.x;
    float r1 = siluf(xo.y*dl.y*sv) * xr.y;
    float r2 = siluf(xo.z*dl.z*sv) * xr.z;
    float r3 = siluf(xo.w*dl.w*sv) * xr.w;
    bf16 hh[4], ll[4];
    splitf(r0, hh[0], ll[0]); splitf(r1, hh[1], ll[1]);
    splitf(r2, hh[2], ll[2]); splitf(r3, hh[3], ll[3]);
    *(uint2*)(g_prP_h + i4*4) = *(uint2*)hh;
    *(uint2*)(g_prP_l + i4*4) = *(uint2*)ll;
}

__global__ void k_maxpool(const float* __restrict__ out, float* __restrict__ pooled)
{
    int b = blockIdx.y;
    int d = blockIdx.x * blockDim.x + threadIdx.x;
    if (d >= DMODEL) return;
    const float* p = out + (size_t)b * LSEQ * DMODEL + d;
    float m = -FLT_MAX;
    for (int l = 0; l < LSEQ; l++) m = fmaxf(m, p[(size_t)l * DMODEL]);
    pooled[b * DMODEL + d] = m;
}

// ------------------------- launch -------------------------
extern "C" void kernel_launch(void* const* d_in, const int* in_sizes, int n_in,
                              void* d_out, int out_size)
{
    const int*   ids    = (const int*)  d_in[0];
    const float* emb    = (const float*)d_in[1];
    const float* rms_w  = (const float*)d_in[2];
    const float* W_in   = (const float*)d_in[3];
    const float* b_in   = (const float*)d_in[4];
    const float* conv_w = (const float*)d_in[5];
    const float* conv_b = (const float*)d_in[6];
    const float* W_cl   = (const float*)d_in[7];
    const float* b_cl   = (const float*)d_in[8];
    const float* fc1_w  = (const float*)d_in[9];
    const float* fc1_b  = (const float*)d_in[10];
    const float* fc2_w  = (const float*)d_in[11];
    const float* fc2_b  = (const float*)d_in[12];
    const float* fc3_w  = (const float*)d_in[13];
    const float* fc3_b  = (const float*)d_in[14];
    const float* W_D    = (const float*)d_in[16];
    const float* b_D    = (const float*)d_in[17];
    const float* W_out  = (const float*)d_in[18];
    const float* b_out  = (const float*)d_in[19];
    float* out = (float*)d_out;

    cudaFuncSetAttribute(k_tc<0,false>, cudaFuncAttributeMaxDynamicSharedMemorySize, SMEM_DYN);
    cudaFuncSetAttribute(k_tc<0,true >, cudaFuncAttributeMaxDynamicSharedMemorySize, SMEM_DYN);
    cudaFuncSetAttribute(k_tc<1,false>, cudaFuncAttributeMaxDynamicSharedMemorySize, SMEM_DYN);
    cudaFuncSetAttribute(k_tc<1,true >, cudaFuncAttributeMaxDynamicSharedMemorySize, SMEM_DYN);
    cudaFuncSetAttribute(k_tc<2,false>, cudaFuncAttributeMaxDynamicSharedMemorySize, SMEM_DYN);

    bf16 *xnh, *xnl, *xcah, *xcal, *xcoh, *xcol, *prh, *prl;
    bf16 *winh, *winl, *wclh, *wcll, *f1h, *f1l, *wdh, *wdl, *woh, *wol;
    bf16 *cah, *cal, *cbh, *cbl;
    float *pxp, *pxco, *pdl, *pxr;
    cudaGetSymbolAddress((void**)&xnh,  g_xnP_h);  cudaGetSymbolAddress((void**)&xnl,  g_xnP_l);
    cudaGetSymbolAddress((void**)&xcah, g_xcaP_h); cudaGetSymbolAddress((void**)&xcal, g_xcaP_l);
    cudaGetSymbolAddress((void**)&xcoh, g_xcoP_h); cudaGetSymbolAddress((void**)&xcol, g_xcoP_l);
    cudaGetSymbolAddress((void**)&prh,  g_prP_h);  cudaGetSymbolAddress((void**)&prl,  g_prP_l);
    cudaGetSymbolAddress((void**)&winh, g_WinS_h); cudaGetSymbolAddress((void**)&winl, g_WinS_l);
    cudaGetSymbolAddress((void**)&wclh, g_WclS_h); cudaGetSymbolAddress((void**)&wcll, g_WclS_l);
    cudaGetSymbolAddress((void**)&f1h,  g_fc1S_h); cudaGetSymbolAddress((void**)&f1l,  g_fc1S_l);
    cudaGetSymbolAddress((void**)&wdh,  g_WDS_h);  cudaGetSymbolAddress((void**)&wdl,  g_WDS_l);
    cudaGetSymbolAddress((void**)&woh,  g_WoS_h);  cudaGetSymbolAddress((void**)&wol,  g_WoS_l);
    cudaGetSymbolAddress((void**)&cah,  g_cA_h);   cudaGetSymbolAddress((void**)&cal,  g_cA_l);
    cudaGetSymbolAddress((void**)&cbh,  g_cB_h);   cudaGetSymbolAddress((void**)&cbl,  g_cB_l);
    cudaGetSymbolAddress((void**)&pxp,  g_xp);
    cudaGetSymbolAddress((void**)&pxco, g_xco);
    cudaGetSymbolAddress((void**)&pdl,  g_dl);
    cudaGetSymbolAddress((void**)&pxr,  g_xr);

    // weight splits (natural [K][N] layout)
    k_wsplit<<<(DMODEL*D2V/4)/256, 256>>>(W_in,  winh, winl);
    k_wsplit<<<(D2V*D2V/4)/256,    256>>>(W_cl,  wclh, wcll);
    k_wsplit<<<(D2V*D2V/4)/256,    256>>>(fc1_w, f1h,  f1l);
    k_wsplit<<<(DMODEL*D2V/4)/256, 256>>>(W_D,   wdh,  wdl);
    k_wsplit<<<(D2V*DMODEL/4)/256, 256>>>(W_out, woh,  wol);
    k_convA<<<dim3(LSEQ/256, LSEQ), 256>>>(conv_w);

    // embed + norms
    k_embed<<<ROWS, 256>>>(ids, emb);
    k_samplestats<<<BATCH, 256>>>();
    k_norm<<<ROWS, 256>>>(rms_w);

    // GEMM1: xp = xn @ W_in + b_in   [8192,768]x[768,1536]
    k_tc<0,false><<<dim3(D2V/BN, ROWS/BM, 1), 256, SMEM_DYN>>>(
        xnh, xnl, winh, winl, b_in, nullptr, pxp, nullptr, nullptr,
        DMODEL, D2V, 0, 0, 0);

    // conv operand gather (k-major)
    k_convB<<<dim3(D2V/256, LSEQ, 3*BATCH), 256>>>();

    // GEMM2 (conv): xca = silu(cA @ cB + conv_b[row]), split-only output
    k_tc<1,true><<<dim3(D2V/BN, LSEQ/BM, BATCH), 256, SMEM_DYN>>>(
        cah, cal, cbh, cbl, nullptr, conv_b, nullptr, xcah, xcal,
        K3, D2V, 0, (long)K3*D2V, (long)LSEQ*D2V);

    // GEMM3: xco = xca @ W_cl + b_cl (float + split)
    k_tc<0,true><<<dim3(D2V/BN, ROWS/BM, 1), 256, SMEM_DYN>>>(
        xcah, xcal, wclh, wcll, b_cl, nullptr, pxco, xcoh, xcol,
        D2V, D2V, 0, 0, 0);

    // GEMM4: delta = softplus(xco @ fc1 + b1)
    k_tc<2,false><<<dim3(D2V/BN, ROWS/BM, 1), 256, SMEM_DYN>>>(
        xcoh, xcol, f1h, f1l, fc1_b, nullptr, pdl, nullptr, nullptr,
        D2V, D2V, 0, 0, 0);

    // s[row] = sum_n Bm*Cm
    k_bcs<<<ROWS, 256>>>(fc2_w, fc2_b, fc3_w, fc3_b);

    // GEMM5: x_res = silu(xn @ W_D + b_D)
    k_tc<1,false><<<dim3(D2V/BN, ROWS/BM, 1), 256, SMEM_DYN>>>(
        xnh, xnl, wdh, wdl, b_D, nullptr, pxr, nullptr, nullptr,
        DMODEL, D2V, 0, 0, 0);

    // prod = silu(xco*delta*s) * x_res  (split for GEMM6)
    k_prod<<<(ROWS * D2V / 4) / 256, 256>>>();

    // GEMM6: out = prod @ W_out + b_out
    k_tc<0,false><<<dim3(DMODEL/BN, ROWS/BM, 1), 256, SMEM_DYN>>>(
        prh, prl, woh, wol, b_out, nullptr, out, nullptr, nullptr,
        D2V, DMODEL, 0, 0, 0);

    if (out_size >= ROWS * DMODEL + BATCH * DMODEL)
        k_maxpool<<<dim3((DMODEL + 255) / 256, BATCH), 256>>>(out, out + (size_t)ROWS * DMODEL);
}